// round 5
// baseline (speedup 1.0000x reference)
#include <cuda_runtime.h>
#include <cuda_fp16.h>
#include <math.h>
#include <stdint.h>

#define BB 8
#define SS 2048
#define DD 512
#define MTOT (BB*SS)

// ---------------- device scratch (no runtime allocation allowed) ------------
__device__ __half g_xh[MTOT*DD];
__device__ __half g_Wth[3][DD*DD], g_Wtl[3][DD*DD];
__device__ __half g_Qh[MTOT*DD];
__device__ __half g_Kh[MTOT*DD], g_Kl[MTOT*DD];
__device__ float  g_Vf[MTOT*DD];
__device__ __half g_Vth[MTOT*DD], g_Vtl[MTOT*DD];
__device__ float  g_S [(long long)BB*SS*SS];
__device__ __half g_Ph[(long long)BB*SS*SS];

// ---------------- helpers ----------------------------------------------------
__device__ __forceinline__ uint32_t smem_u32(const void* p){
    uint32_t a;
    asm("{ .reg .u64 t; cvta.to.shared.u64 t, %1; cvt.u32.u64 %0, t; }" : "=r"(a) : "l"(p));
    return a;
}
__device__ __forceinline__ void cpa16(uint32_t dst, const void* src){
    asm volatile("cp.async.cg.shared.global [%0], [%1], 16;" :: "r"(dst), "l"(src));
}
__device__ __forceinline__ void cpa_commit(){ asm volatile("cp.async.commit_group;"); }
template<int N> __device__ __forceinline__ void cpa_wait(){
    asm volatile("cp.async.wait_group %0;" :: "n"(N));
}
__device__ __forceinline__ void ldm_x4(uint32_t* r, uint32_t addr){
    asm volatile("ldmatrix.sync.aligned.m8n8.x4.shared.b16 {%0,%1,%2,%3}, [%4];"
        : "=r"(r[0]), "=r"(r[1]), "=r"(r[2]), "=r"(r[3]) : "r"(addr));
}
// f32-accumulate MMA (main term)
__device__ __forceinline__ void mma16816(float* d, const uint32_t* a, uint32_t b0, uint32_t b1){
    asm volatile("mma.sync.aligned.m16n8k16.row.col.f32.f16.f16.f32 "
        "{%0,%1,%2,%3},{%4,%5,%6,%7},{%8,%9},{%0,%1,%2,%3};"
        : "+f"(d[0]), "+f"(d[1]), "+f"(d[2]), "+f"(d[3])
        : "r"(a[0]), "r"(a[1]), "r"(a[2]), "r"(a[3]), "r"(b0), "r"(b1));
}
// f16-accumulate MMA (small correction term; O(eps^2) extra error)
__device__ __forceinline__ void mma16816h(uint32_t* d, const uint32_t* a, uint32_t b0, uint32_t b1){
    asm volatile("mma.sync.aligned.m16n8k16.row.col.f16.f16.f16.f16 "
        "{%0,%1},{%2,%3,%4,%5},{%6,%7},{%0,%1};"
        : "+r"(d[0]), "+r"(d[1])
        : "r"(a[0]), "r"(a[1]), "r"(a[2]), "r"(a[3]), "r"(b0), "r"(b1));
}

// ---------------- smem layout -------------------------------------------------
// Per matrix block: 128 rows x 80 bytes (64B data + 16B pad) -> conflict-free ldmatrix.
#define PITCH   80
#define MATB    (128*PITCH)      // 10240 bytes
#define STAGEB  (3*MATB)         // A, Bh, Bl
#define SMEMB   (2*STAGEB)       // 61440

// ---------------- 2-term split-fp16 tensor-core GEMM --------------------------
// C = A * (Bh+Bl)^T ; A plain fp16 [M,K] K-major, B split [N,K] K-major.
// Main term f32-acc, correction term f16-acc.
// EPI 0: Cf = alpha*D + bias (fp32)
// EPI 1: (Ch,Cl) = split(D + bias)  (fp16 hi/lo)
// EPI 2: Ch = fp16(D + bias)        (hi only)
template<int EPI>
__global__ void __launch_bounds__(256)
gemm_mma(const __half* __restrict__ Ah,
         const __half* __restrict__ Bh, const __half* __restrict__ Bl,
         const float* __restrict__ bias,
         float* __restrict__ Cf, __half* __restrict__ Ch, __half* __restrict__ Cl,
         int N, int K, float alpha,
         long long sA, long long sB, long long sC)
{
    extern __shared__ char smem[];
    const uint32_t sb = smem_u32(smem);
    const int tid = threadIdx.x;
    const int wid = tid >> 5, lane = tid & 31;
    const int wr = wid >> 2, wc = wid & 3;          // warp grid 2x4
    const int wm0 = wr * 64, wn0 = wc * 32;

    const int row0 = blockIdx.y << 7, col0 = blockIdx.x << 7;
    const long long zA = (long long)blockIdx.z * sA;
    const long long zB = (long long)blockIdx.z * sB;
    const long long zC = (long long)blockIdx.z * sC;

    const __half* gsrc[3] = { Ah + zA + (long long)row0 * K,
                              Bh + zB + (long long)col0 * K,
                              Bl + zB + (long long)col0 * K };

    // loader: per matrix 128 rows x 4 x 16B units = 512 slots, 2 iters of 256 threads
    const int lrow0 = tid >> 2;          // 0..63
    const int lu    = tid & 3;           // 16B unit

    float    acc [4][4][4];              // main (f32)
    uint32_t accc[4][4][2];              // correction (f16x2 pairs: {c0,c1},{c2,c3})
#pragma unroll
    for (int i = 0; i < 4; i++)
#pragma unroll
        for (int j = 0; j < 4; j++) {
#pragma unroll
            for (int q = 0; q < 4; q++) acc[i][j][q] = 0.0f;
            accc[i][j][0] = 0u; accc[i][j][1] = 0u;
        }

    const int NC = K >> 5;   // chunks of 32

    auto load_chunk = [&](int stage, int kc) {
        const uint32_t sdst = sb + stage * STAGEB;
#pragma unroll
        for (int m = 0; m < 3; m++) {
            const __half* g = gsrc[m] + kc * 32;
#pragma unroll
            for (int it = 0; it < 2; it++) {
                const int row = lrow0 + it * 64;
                cpa16(sdst + m * MATB + row * PITCH + lu * 16,
                      g + (long long)row * K + lu * 8);
            }
        }
    };

    load_chunk(0, 0);
    cpa_commit();

    for (int kc = 0; kc < NC; kc++) {
        const int s = kc & 1;
        if (kc + 1 < NC) { load_chunk(s ^ 1, kc + 1); cpa_commit(); cpa_wait<1>(); }
        else             { cpa_wait<0>(); }
        __syncthreads();

        const uint32_t sAh = sb + s * STAGEB;
        const uint32_t sBh = sAh + MATB;
        const uint32_t sBl = sAh + 2 * MATB;

        const int lr = lane & 15;            // ldmatrix row-in-tile
        const int lc = (lane >> 4) * 16;     // k8 select (byte offset)

#pragma unroll
        for (int k16 = 0; k16 < 2; k16++) {
            const uint32_t kb = k16 * 32 + lc;
            uint32_t ah[4][4], bh[2][4], bl[2][4];
#pragma unroll
            for (int i = 0; i < 4; i++) {
                const uint32_t ro = (uint32_t)(wm0 + i * 16 + lr) * PITCH + kb;
                ldm_x4(ah[i], sAh + ro);
            }
#pragma unroll
            for (int jj = 0; jj < 2; jj++) {
                const uint32_t ro = (uint32_t)(wn0 + jj * 16 + lr) * PITCH + kb;
                ldm_x4(bh[jj], sBh + ro);
                ldm_x4(bl[jj], sBl + ro);
            }
#pragma unroll
            for (int i = 0; i < 4; i++) {
#pragma unroll
                for (int j = 0; j < 4; j++) {
                    const int jj = j >> 1, sel = j & 1;
                    mma16816 (acc [i][j], ah[i], bh[jj][sel], bh[jj][sel + 2]);
                    mma16816h(accc[i][j], ah[i], bl[jj][sel], bl[jj][sel + 2]);
                }
            }
        }
        __syncthreads();
    }

    // ---------------- epilogue ----------------
    const int er = lane >> 2;            // 0..7
    const int ec = (lane & 3) * 2;       // 0,2,4,6
#pragma unroll
    for (int i = 0; i < 4; i++) {
#pragma unroll
        for (int j = 0; j < 4; j++) {
            const int col = col0 + wn0 + j * 8 + ec;
#pragma unroll
            for (int half_m = 0; half_m < 2; half_m++) {
                const int row = row0 + wm0 + i * 16 + er + half_m * 8;
                const __half2 cc = *(const __half2*)&accc[i][j][half_m];
                const float d0 = acc[i][j][half_m * 2 + 0] + __low2float(cc);
                const float d1 = acc[i][j][half_m * 2 + 1] + __high2float(cc);
                if (EPI == 0) {
                    float2 v;
                    v.x = d0 * alpha; v.y = d1 * alpha;
                    if (bias) { v.x += bias[col]; v.y += bias[col + 1]; }
                    *(float2*)(Cf + zC + (long long)row * N + col) = v;
                } else if (EPI == 1) {
                    float f0 = d0 + bias[col];
                    float f1 = d1 + bias[col + 1];
                    __half h0 = __float2half_rn(f0), h1 = __float2half_rn(f1);
                    __half l0 = __float2half_rn(f0 - __half2float(h0));
                    __half l1 = __float2half_rn(f1 - __half2float(h1));
                    *(__half2*)(Ch + zC + (long long)row * N + col) = __halves2half2(h0, h1);
                    *(__half2*)(Cl + zC + (long long)row * N + col) = __halves2half2(l0, l1);
                } else {
                    float f0 = d0 + bias[col];
                    float f1 = d1 + bias[col + 1];
                    *(__half2*)(Ch + zC + (long long)row * N + col) =
                        __halves2half2(__float2half_rn(f0), __float2half_rn(f1));
                }
            }
        }
    }
}

// ---------------- elementwise fp32 -> fp16 (hi only) -------------------------
__global__ void __launch_bounds__(256)
cvt_f32_f16(const float* __restrict__ s, __half* __restrict__ h, int n4)
{
    int i = blockIdx.x * 256 + threadIdx.x;
    if (i >= n4) return;
    float4 v = ((const float4*)s)[i];
    *(__half2*)(h + 4*i)     = __halves2half2(__float2half_rn(v.x), __float2half_rn(v.y));
    *(__half2*)(h + 4*i + 2) = __halves2half2(__float2half_rn(v.z), __float2half_rn(v.w));
}

// ---------------- transpose + split: src fp32 [R,C] -> dst (hi,lo) [C,R] -----
__global__ void __launch_bounds__(256)
transpose_split(const float* __restrict__ src, __half* __restrict__ dh, __half* __restrict__ dl,
                int R, int C, long long sS, long long sD)
{
    __shared__ float t[32][33];
    const float* S = src + (long long)blockIdx.z * sS;
    __half* DH = dh + (long long)blockIdx.z * sD;
    __half* DL = dl + (long long)blockIdx.z * sD;
    const int c0 = blockIdx.x * 32, r0 = blockIdx.y * 32;
    const int tx = threadIdx.x, ty = threadIdx.y;   // (32, 8)
#pragma unroll
    for (int k = 0; k < 4; k++)
        t[ty + 8*k][tx] = S[(long long)(r0 + ty + 8*k) * C + c0 + tx];
    __syncthreads();
#pragma unroll
    for (int k = 0; k < 4; k++) {
        float f = t[tx][ty + 8*k];
        __half h = __float2half_rn(f);
        __half l = __float2half_rn(f - __half2float(h));
        long long o = (long long)(c0 + ty + 8*k) * R + r0 + tx;
        DH[o] = h; DL[o] = l;
    }
}

// ---------------- row softmax (2048 cols), fp32 in -> plain fp16 out ----------
__global__ void __launch_bounds__(256)
softmax2048(const float* __restrict__ S, __half* __restrict__ Ph)
{
    const long long rb = (long long)blockIdx.x * SS;
    const int t = threadIdx.x;
    float v[8];
    float m = -INFINITY;
#pragma unroll
    for (int i = 0; i < 8; i++) { v[i] = S[rb + t + i*256]; m = fmaxf(m, v[i]); }

    __shared__ float red[8];
#pragma unroll
    for (int o = 16; o > 0; o >>= 1) m = fmaxf(m, __shfl_xor_sync(0xffffffffu, m, o));
    if ((t & 31) == 0) red[t >> 5] = m;
    __syncthreads();
    if (t < 32) {
        float mm = (t < 8) ? red[t] : -INFINITY;
#pragma unroll
        for (int o = 4; o > 0; o >>= 1) mm = fmaxf(mm, __shfl_xor_sync(0xffffffffu, mm, o));
        if (t == 0) red[0] = mm;
    }
    __syncthreads();
    m = red[0];
    __syncthreads();

    float sum = 0.0f;
#pragma unroll
    for (int i = 0; i < 8; i++) { v[i] = __expf(v[i] - m); sum += v[i]; }
#pragma unroll
    for (int o = 16; o > 0; o >>= 1) sum += __shfl_xor_sync(0xffffffffu, sum, o);
    if ((t & 31) == 0) red[t >> 5] = sum;
    __syncthreads();
    if (t < 32) {
        float ss = (t < 8) ? red[t] : 0.0f;
#pragma unroll
        for (int o = 4; o > 0; o >>= 1) ss += __shfl_xor_sync(0xffffffffu, ss, o);
        if (t == 0) red[0] = ss;
    }
    __syncthreads();
    const float inv = 1.0f / red[0];

#pragma unroll
    for (int i = 0; i < 8; i++)
        Ph[rb + t + i*256] = __float2half_rn(v[i] * inv);
}

// -----------------------------------------------------------------------------
extern "C" void kernel_launch(void* const* d_in, const int* in_sizes, int n_in,
                              void* d_out, int out_size)
{
    (void)in_sizes; (void)n_in; (void)out_size;
    const float* x  = (const float*)d_in[0];
    const float* Wq = (const float*)d_in[1];
    const float* bq = (const float*)d_in[2];
    const float* Wk = (const float*)d_in[3];
    const float* bk = (const float*)d_in[4];
    const float* Wv = (const float*)d_in[5];
    const float* bv = (const float*)d_in[6];
    float* out = (float*)d_out;

    __half *xh, *Wth, *Wtl, *Qh, *Kh, *Kl, *Vth, *Vtl, *Ph;
    float *Vf, *Sc;
    cudaGetSymbolAddress((void**)&xh,  g_xh);
    cudaGetSymbolAddress((void**)&Wth, g_Wth); cudaGetSymbolAddress((void**)&Wtl, g_Wtl);
    cudaGetSymbolAddress((void**)&Qh,  g_Qh);
    cudaGetSymbolAddress((void**)&Kh,  g_Kh);  cudaGetSymbolAddress((void**)&Kl,  g_Kl);
    cudaGetSymbolAddress((void**)&Vf,  g_Vf);
    cudaGetSymbolAddress((void**)&Vth, g_Vth); cudaGetSymbolAddress((void**)&Vtl, g_Vtl);
    cudaGetSymbolAddress((void**)&Sc,  g_S);
    cudaGetSymbolAddress((void**)&Ph,  g_Ph);

    cudaFuncSetAttribute(gemm_mma<0>, cudaFuncAttributeMaxDynamicSharedMemorySize, SMEMB);
    cudaFuncSetAttribute(gemm_mma<1>, cudaFuncAttributeMaxDynamicSharedMemorySize, SMEMB);
    cudaFuncSetAttribute(gemm_mma<2>, cudaFuncAttributeMaxDynamicSharedMemorySize, SMEMB);

    const float scale = 1.0f / sqrtf((float)DD);

    // 1) x -> fp16 (hi only; correction rides on the weight side)
    {
        int n4 = MTOT * DD / 4;
        cvt_f32_f16<<<(n4 + 255) / 256, 256>>>(x, xh, n4);
    }
    // 2) transpose+split weights: Wt[n][k] = W[k][n]
    {
        dim3 tb(32, 8), tg(DD/32, DD/32, 1);
        transpose_split<<<tg, tb>>>(Wq, Wth + 0*DD*DD, Wtl + 0*DD*DD, DD, DD, 0, 0);
        transpose_split<<<tg, tb>>>(Wk, Wth + 1*DD*DD, Wtl + 1*DD*DD, DD, DD, 0, 0);
        transpose_split<<<tg, tb>>>(Wv, Wth + 2*DD*DD, Wtl + 2*DD*DD, DD, DD, 0, 0);
    }
    // 3) projections (M=16384, N=512, K=512), 2-term (B split)
    {
        dim3 g(DD/128, MTOT/128, 1);
        gemm_mma<2><<<g, 256, SMEMB>>>(xh, Wth + 0*DD*DD, Wtl + 0*DD*DD, bq,
                                       nullptr, Qh, nullptr, DD, DD, 1.0f, 0, 0, 0);
        gemm_mma<1><<<g, 256, SMEMB>>>(xh, Wth + 1*DD*DD, Wtl + 1*DD*DD, bk,
                                       nullptr, Kh, Kl, DD, DD, 1.0f, 0, 0, 0);
        gemm_mma<0><<<g, 256, SMEMB>>>(xh, Wth + 2*DD*DD, Wtl + 2*DD*DD, bv,
                                       Vf, nullptr, nullptr, DD, DD, 1.0f, 0, 0, 0);
    }
    // 4) transpose+split V per batch: Vf [s,e] -> Vt [e,s]
    {
        dim3 tb(32, 8), tg(DD/32, SS/32, BB);
        transpose_split<<<tg, tb>>>(Vf, Vth, Vtl, SS, DD,
                                    (long long)SS*DD, (long long)DD*SS);
    }
    // 5) scores = scale * Q @ K^T per batch (M=N=2048, K=512), 2-term
    {
        dim3 g(SS/128, SS/128, BB);
        gemm_mma<0><<<g, 256, SMEMB>>>(Qh, Kh, Kl, nullptr,
                                       Sc, nullptr, nullptr, SS, DD, scale,
                                       (long long)SS*DD, (long long)SS*DD,
                                       (long long)SS*SS);
    }
    // 6) softmax -> P plain fp16
    softmax2048<<<BB*SS, 256>>>(Sc, Ph);
    // 7) out = P @ V per batch (M=2048, N=512, K=2048), 2-term
    {
        dim3 g(DD/128, SS/128, BB);
        gemm_mma<0><<<g, 256, SMEMB>>>(Ph, Vth, Vtl, nullptr,
                                       out, nullptr, nullptr, DD, SS, 1.0f,
                                       (long long)SS*SS, (long long)DD*SS,
                                       (long long)SS*DD);
    }
}

// round 6
// speedup vs baseline: 1.5131x; 1.5131x over previous
#include <cuda_runtime.h>
#include <cuda_fp16.h>
#include <math.h>
#include <stdint.h>

#define BB 8
#define SS 2048
#define DD 512
#define MTOT (BB*SS)

// ---------------- device scratch (no runtime allocation allowed) ------------
__device__ __half g_xh[MTOT*DD];
__device__ __half g_Wth[3][DD*DD], g_Wtl[3][DD*DD];
__device__ __half g_Qh[MTOT*DD];
__device__ __half g_Kh[MTOT*DD];
__device__ float  g_Vf[MTOT*DD];
__device__ __half g_Vth[MTOT*DD];
__device__ float  g_S [(long long)BB*SS*SS];
__device__ __half g_Ph[(long long)BB*SS*SS];

// ---------------- helpers ----------------------------------------------------
__device__ __forceinline__ uint32_t smem_u32(const void* p){
    uint32_t a;
    asm("{ .reg .u64 t; cvta.to.shared.u64 t, %1; cvt.u32.u64 %0, t; }" : "=r"(a) : "l"(p));
    return a;
}
__device__ __forceinline__ void cpa16(uint32_t dst, const void* src){
    asm volatile("cp.async.cg.shared.global [%0], [%1], 16;" :: "r"(dst), "l"(src));
}
__device__ __forceinline__ void cpa_commit(){ asm volatile("cp.async.commit_group;"); }
template<int N> __device__ __forceinline__ void cpa_wait(){
    asm volatile("cp.async.wait_group %0;" :: "n"(N));
}
__device__ __forceinline__ void ldm_x4(uint32_t* r, uint32_t addr){
    asm volatile("ldmatrix.sync.aligned.m8n8.x4.shared.b16 {%0,%1,%2,%3}, [%4];"
        : "=r"(r[0]), "=r"(r[1]), "=r"(r[2]), "=r"(r[3]) : "r"(addr));
}
__device__ __forceinline__ void mma16816(float* d, const uint32_t* a, uint32_t b0, uint32_t b1){
    asm volatile("mma.sync.aligned.m16n8k16.row.col.f32.f16.f16.f32 "
        "{%0,%1,%2,%3},{%4,%5,%6,%7},{%8,%9},{%0,%1,%2,%3};"
        : "+f"(d[0]), "+f"(d[1]), "+f"(d[2]), "+f"(d[3])
        : "r"(a[0]), "r"(a[1]), "r"(a[2]), "r"(a[3]), "r"(b0), "r"(b1));
}

// ---------------- smem layout -------------------------------------------------
// Per matrix block: 128 rows x 80 bytes (64B data + 16B pad) -> conflict-free ldmatrix.
#define PITCH   80
#define MATB    (128*PITCH)      // 10240 bytes

// ---------------- tensor-core GEMM ---------------------------------------------
// BSPLIT=1: C = A*(Bh+Bl)^T  (2-term, both f32-acc), NSTAGE should be 2
// BSPLIT=0: C = A* Bh    ^T  (1-term plain fp16),    NSTAGE should be 3
// A:[M,K] K-major fp16, B:[N,K] K-major. 256 threads, 8 warps, warp tile 64x32.
// EPI 0: Cf = alpha*D + bias (fp32)
// EPI 2: Ch = fp16(D + bias) (fp16)
template<int BSPLIT, int EPI, int NSTAGE>
__global__ void __launch_bounds__(256, 2)
gemm_mma(const __half* __restrict__ Ah,
         const __half* __restrict__ Bh, const __half* __restrict__ Bl,
         const float* __restrict__ bias,
         float* __restrict__ Cf, __half* __restrict__ Ch,
         int N, int K, float alpha,
         long long sA, long long sB, long long sC)
{
    constexpr int NMAT = 2 + BSPLIT;
    constexpr uint32_t STAGEB = NMAT * MATB;

    extern __shared__ char smem[];
    const uint32_t sb = smem_u32(smem);
    const int tid = threadIdx.x;
    const int wid = tid >> 5, lane = tid & 31;
    const int wr = wid >> 2, wc = wid & 3;          // warp grid 2x4
    const int wm0 = wr * 64, wn0 = wc * 32;

    const int row0 = blockIdx.y << 7, col0 = blockIdx.x << 7;
    const long long zA = (long long)blockIdx.z * sA;
    const long long zB = (long long)blockIdx.z * sB;
    const long long zC = (long long)blockIdx.z * sC;

    const __half* gsrc[NMAT];
    gsrc[0] = Ah + zA + (long long)row0 * K;
    gsrc[1] = Bh + zB + (long long)col0 * K;
    if (BSPLIT) gsrc[2] = Bl + zB + (long long)col0 * K;

    // loader: per matrix 128 rows x 4 x 16B units = 512 slots, 2 iters of 256 threads
    const int lrow0 = tid >> 2;          // 0..63
    const int lu    = tid & 3;           // 16B unit

    float acc[4][4][4];
#pragma unroll
    for (int i = 0; i < 4; i++)
#pragma unroll
        for (int j = 0; j < 4; j++)
#pragma unroll
            for (int q = 0; q < 4; q++) acc[i][j][q] = 0.0f;

    const int NC = K >> 5;   // chunks of 32

    auto load_chunk = [&](int stage, int kc) {
        const uint32_t sdst = sb + stage * STAGEB;
#pragma unroll
        for (int m = 0; m < NMAT; m++) {
            const __half* g = gsrc[m] + kc * 32;
#pragma unroll
            for (int it = 0; it < 2; it++) {
                const int row = lrow0 + it * 64;
                cpa16(sdst + m * MATB + row * PITCH + lu * 16,
                      g + (long long)row * K + lu * 8);
            }
        }
    };

    // prologue: fill NSTAGE-1 stages (one commit group each)
#pragma unroll
    for (int s = 0; s < NSTAGE - 1; s++) {
        if (s < NC) load_chunk(s, s);
        cpa_commit();
    }

    for (int kc = 0; kc < NC; kc++) {
        const int s = kc % NSTAGE;
        const int pre = kc + NSTAGE - 1;
        if (pre < NC) load_chunk(pre % NSTAGE, pre);
        cpa_commit();                       // one group per iter (possibly empty)
        cpa_wait<NSTAGE - 1>();             // chunk kc complete (FIFO groups)
        __syncthreads();

        const uint32_t sAh = sb + s * STAGEB;
        const uint32_t sBh = sAh + MATB;
        const uint32_t sBl = sAh + 2 * MATB;

        const int lr = lane & 15;            // ldmatrix row-in-tile
        const int lc = (lane >> 4) * 16;     // k8 select (byte offset)

#pragma unroll
        for (int k16 = 0; k16 < 2; k16++) {
            const uint32_t kb = k16 * 32 + lc;
            uint32_t ah[4][4], bh[2][4], bl[2][4];
#pragma unroll
            for (int i = 0; i < 4; i++) {
                const uint32_t ro = (uint32_t)(wm0 + i * 16 + lr) * PITCH + kb;
                ldm_x4(ah[i], sAh + ro);
            }
#pragma unroll
            for (int jj = 0; jj < 2; jj++) {
                const uint32_t ro = (uint32_t)(wn0 + jj * 16 + lr) * PITCH + kb;
                ldm_x4(bh[jj], sBh + ro);
                if (BSPLIT) ldm_x4(bl[jj], sBl + ro);
            }
#pragma unroll
            for (int i = 0; i < 4; i++) {
#pragma unroll
                for (int j = 0; j < 4; j++) {
                    const int jj = j >> 1, sel = j & 1;
                    mma16816(acc[i][j], ah[i], bh[jj][sel], bh[jj][sel + 2]);
                    if (BSPLIT)
                        mma16816(acc[i][j], ah[i], bl[jj][sel], bl[jj][sel + 2]);
                }
            }
        }
        __syncthreads();
    }

    // ---------------- epilogue ----------------
    const int er = lane >> 2;            // 0..7
    const int ec = (lane & 3) * 2;       // 0,2,4,6
#pragma unroll
    for (int i = 0; i < 4; i++) {
#pragma unroll
        for (int j = 0; j < 4; j++) {
            const int col = col0 + wn0 + j * 8 + ec;
#pragma unroll
            for (int half_m = 0; half_m < 2; half_m++) {
                const int row = row0 + wm0 + i * 16 + er + half_m * 8;
                const float d0 = acc[i][j][half_m * 2 + 0];
                const float d1 = acc[i][j][half_m * 2 + 1];
                if (EPI == 0) {
                    float2 v;
                    v.x = d0 * alpha; v.y = d1 * alpha;
                    if (bias) { v.x += bias[col]; v.y += bias[col + 1]; }
                    *(float2*)(Cf + zC + (long long)row * N + col) = v;
                } else {
                    float f0 = d0 + bias[col];
                    float f1 = d1 + bias[col + 1];
                    *(__half2*)(Ch + zC + (long long)row * N + col) =
                        __halves2half2(__float2half_rn(f0), __float2half_rn(f1));
                }
            }
        }
    }
}

// ---------------- elementwise fp32 -> fp16 ------------------------------------
__global__ void __launch_bounds__(256)
cvt_f32_f16(const float* __restrict__ s, __half* __restrict__ h, int n4)
{
    int i = blockIdx.x * 256 + threadIdx.x;
    if (i >= n4) return;
    float4 v = ((const float4*)s)[i];
    *(__half2*)(h + 4*i)     = __halves2half2(__float2half_rn(v.x), __float2half_rn(v.y));
    *(__half2*)(h + 4*i + 2) = __halves2half2(__float2half_rn(v.z), __float2half_rn(v.w));
}

// ---------------- transpose (+optional split): fp32 [R,C] -> fp16 [C,R] -------
__global__ void __launch_bounds__(256)
transpose_cvt(const float* __restrict__ src, __half* __restrict__ dh, __half* __restrict__ dl,
              int R, int C, long long sS, long long sD)
{
    __shared__ float t[32][33];
    const float* S = src + (long long)blockIdx.z * sS;
    __half* DH = dh + (long long)blockIdx.z * sD;
    const int c0 = blockIdx.x * 32, r0 = blockIdx.y * 32;
    const int tx = threadIdx.x, ty = threadIdx.y;   // (32, 8)
#pragma unroll
    for (int k = 0; k < 4; k++)
        t[ty + 8*k][tx] = S[(long long)(r0 + ty + 8*k) * C + c0 + tx];
    __syncthreads();
    if (dl) {
        __half* DL = dl + (long long)blockIdx.z * sD;
#pragma unroll
        for (int k = 0; k < 4; k++) {
            float f = t[tx][ty + 8*k];
            __half h = __float2half_rn(f);
            __half l = __float2half_rn(f - __half2float(h));
            long long o = (long long)(c0 + ty + 8*k) * R + r0 + tx;
            DH[o] = h; DL[o] = l;
        }
    } else {
#pragma unroll
        for (int k = 0; k < 4; k++) {
            long long o = (long long)(c0 + ty + 8*k) * R + r0 + tx;
            DH[o] = __float2half_rn(t[tx][ty + 8*k]);
        }
    }
}

// ---------------- row softmax (2048 cols), fp32 in -> plain fp16 out ----------
__global__ void __launch_bounds__(256)
softmax2048(const float* __restrict__ S, __half* __restrict__ Ph)
{
    const long long rb = (long long)blockIdx.x * SS;
    const int t = threadIdx.x;
    float v[8];
    float m = -INFINITY;
#pragma unroll
    for (int i = 0; i < 8; i++) { v[i] = S[rb + t + i*256]; m = fmaxf(m, v[i]); }

    __shared__ float red[8];
#pragma unroll
    for (int o = 16; o > 0; o >>= 1) m = fmaxf(m, __shfl_xor_sync(0xffffffffu, m, o));
    if ((t & 31) == 0) red[t >> 5] = m;
    __syncthreads();
    if (t < 32) {
        float mm = (t < 8) ? red[t] : -INFINITY;
#pragma unroll
        for (int o = 4; o > 0; o >>= 1) mm = fmaxf(mm, __shfl_xor_sync(0xffffffffu, mm, o));
        if (t == 0) red[0] = mm;
    }
    __syncthreads();
    m = red[0];
    __syncthreads();

    float sum = 0.0f;
#pragma unroll
    for (int i = 0; i < 8; i++) { v[i] = __expf(v[i] - m); sum += v[i]; }
#pragma unroll
    for (int o = 16; o > 0; o >>= 1) sum += __shfl_xor_sync(0xffffffffu, sum, o);
    if ((t & 31) == 0) red[t >> 5] = sum;
    __syncthreads();
    if (t < 32) {
        float ss = (t < 8) ? red[t] : 0.0f;
#pragma unroll
        for (int o = 4; o > 0; o >>= 1) ss += __shfl_xor_sync(0xffffffffu, ss, o);
        if (t == 0) red[0] = ss;
    }
    __syncthreads();
    const float inv = 1.0f / red[0];

#pragma unroll
    for (int i = 0; i < 8; i++)
        Ph[rb + t + i*256] = __float2half_rn(v[i] * inv);
}

// -----------------------------------------------------------------------------
extern "C" void kernel_launch(void* const* d_in, const int* in_sizes, int n_in,
                              void* d_out, int out_size)
{
    (void)in_sizes; (void)n_in; (void)out_size;
    const float* x  = (const float*)d_in[0];
    const float* Wq = (const float*)d_in[1];
    const float* bq = (const float*)d_in[2];
    const float* Wk = (const float*)d_in[3];
    const float* bk = (const float*)d_in[4];
    const float* Wv = (const float*)d_in[5];
    const float* bv = (const float*)d_in[6];
    float* out = (float*)d_out;

    __half *xh, *Wth, *Wtl, *Qh, *Kh, *Vth, *Ph;
    float *Vf, *Sc;
    cudaGetSymbolAddress((void**)&xh,  g_xh);
    cudaGetSymbolAddress((void**)&Wth, g_Wth); cudaGetSymbolAddress((void**)&Wtl, g_Wtl);
    cudaGetSymbolAddress((void**)&Qh,  g_Qh);
    cudaGetSymbolAddress((void**)&Kh,  g_Kh);
    cudaGetSymbolAddress((void**)&Vf,  g_Vf);
    cudaGetSymbolAddress((void**)&Vth, g_Vth);
    cudaGetSymbolAddress((void**)&Sc,  g_S);
    cudaGetSymbolAddress((void**)&Ph,  g_Ph);

    const int SMEM_P = 2 * 3 * MATB;   // projections: 2 stages x 3 mats = 61440
    const int SMEM_1 = 3 * 2 * MATB;   // 1-term:      3 stages x 2 mats = 61440
    cudaFuncSetAttribute((const void*)gemm_mma<1,0,2>, cudaFuncAttributeMaxDynamicSharedMemorySize, SMEM_P);
    cudaFuncSetAttribute((const void*)gemm_mma<1,2,2>, cudaFuncAttributeMaxDynamicSharedMemorySize, SMEM_P);
    cudaFuncSetAttribute((const void*)gemm_mma<0,0,3>, cudaFuncAttributeMaxDynamicSharedMemorySize, SMEM_1);

    const float scale = 1.0f / sqrtf((float)DD);

    // 1-3) transpose+split weights first (so ncu -s 5 lands on a GEMM)
    {
        dim3 tb(32, 8), tg(DD/32, DD/32, 1);
        transpose_cvt<<<tg, tb>>>(Wq, Wth + 0*DD*DD, Wtl + 0*DD*DD, DD, DD, 0, 0);
        transpose_cvt<<<tg, tb>>>(Wk, Wth + 1*DD*DD, Wtl + 1*DD*DD, DD, DD, 0, 0);
        transpose_cvt<<<tg, tb>>>(Wv, Wth + 2*DD*DD, Wtl + 2*DD*DD, DD, DD, 0, 0);
    }
    // 4) x -> fp16
    {
        int n4 = MTOT * DD / 4;
        cvt_f32_f16<<<(n4 + 255) / 256, 256>>>(x, xh, n4);
    }
    // 5-7) projections (M=16384, N=512, K=512), 2-term (W split), f32-acc both
    {
        dim3 g(DD/128, MTOT/128, 1);
        gemm_mma<1,2,2><<<g, 256, SMEM_P>>>(xh, Wth + 0*DD*DD, Wtl + 0*DD*DD, bq,
                                            nullptr, Qh, DD, DD, 1.0f, 0, 0, 0);
        gemm_mma<1,2,2><<<g, 256, SMEM_P>>>(xh, Wth + 1*DD*DD, Wtl + 1*DD*DD, bk,
                                            nullptr, Kh, DD, DD, 1.0f, 0, 0, 0);
        gemm_mma<1,0,2><<<g, 256, SMEM_P>>>(xh, Wth + 2*DD*DD, Wtl + 2*DD*DD, bv,
                                            Vf, nullptr, DD, DD, 1.0f, 0, 0, 0);
    }
    // 8) transpose V per batch: Vf [s,e] -> Vt [e,s] (fp16 hi only)
    {
        dim3 tb(32, 8), tg(DD/32, SS/32, BB);
        transpose_cvt<<<tg, tb>>>(Vf, Vth, nullptr, SS, DD,
                                  (long long)SS*DD, (long long)DD*SS);
    }
    // 9) scores = scale * Q @ K^T per batch (M=N=2048, K=512), 1-term fp16
    {
        dim3 g(SS/128, SS/128, BB);
        gemm_mma<0,0,3><<<g, 256, SMEM_1>>>(Qh, Kh, nullptr, nullptr,
                                            Sc, nullptr, SS, DD, scale,
                                            (long long)SS*DD, (long long)SS*DD,
                                            (long long)SS*SS);
    }
    // 10) softmax -> P plain fp16
    softmax2048<<<BB*SS, 256>>>(Sc, Ph);
    // 11) out = P @ V per batch (M=2048, N=512, K=2048), 1-term fp16
    {
        dim3 g(DD/128, SS/128, BB);
        gemm_mma<0,0,3><<<g, 256, SMEM_1>>>(Ph, Vth, nullptr, nullptr,
                                            out, nullptr, DD, SS, 1.0f,
                                            (long long)SS*SS, (long long)DD*SS,
                                            (long long)SS*DD);
    }
}

// round 7
// speedup vs baseline: 1.6079x; 1.0627x over previous
#include <cuda_runtime.h>
#include <cuda_fp16.h>
#include <math.h>
#include <stdint.h>

#define BB 8
#define SS 2048
#define DD 512
#define MTOT (BB*SS)

// ---------------- device scratch (no runtime allocation allowed) ------------
__device__ __half g_xh[MTOT*DD];
__device__ __half g_Wth[3][DD*DD], g_Wtl[3][DD*DD];
__device__ __half g_Qh[MTOT*DD];
__device__ __half g_Kh[MTOT*DD];
__device__ float  g_Vf[MTOT*DD];
__device__ __half g_Vth[MTOT*DD];
__device__ __half g_Sc[(long long)BB*SS*SS];     // fp16 scores (64 MB)
__device__ float  g_rowm[MTOT], g_rowinv[MTOT];  // softmax row stats

// ---------------- helpers ----------------------------------------------------
__device__ __forceinline__ uint32_t smem_u32(const void* p){
    uint32_t a;
    asm("{ .reg .u64 t; cvta.to.shared.u64 t, %1; cvt.u32.u64 %0, t; }" : "=r"(a) : "l"(p));
    return a;
}
__device__ __forceinline__ void cpa16(uint32_t dst, const void* src){
    asm volatile("cp.async.cg.shared.global [%0], [%1], 16;" :: "r"(dst), "l"(src));
}
__device__ __forceinline__ void cpa_commit(){ asm volatile("cp.async.commit_group;"); }
template<int N> __device__ __forceinline__ void cpa_wait(){
    asm volatile("cp.async.wait_group %0;" :: "n"(N));
}
__device__ __forceinline__ void ldm_x4(uint32_t* r, uint32_t addr){
    asm volatile("ldmatrix.sync.aligned.m8n8.x4.shared.b16 {%0,%1,%2,%3}, [%4];"
        : "=r"(r[0]), "=r"(r[1]), "=r"(r[2]), "=r"(r[3]) : "r"(addr));
}
__device__ __forceinline__ void mma16816(float* d, const uint32_t* a, uint32_t b0, uint32_t b1){
    asm volatile("mma.sync.aligned.m16n8k16.row.col.f32.f16.f16.f32 "
        "{%0,%1,%2,%3},{%4,%5,%6,%7},{%8,%9},{%0,%1,%2,%3};"
        : "+f"(d[0]), "+f"(d[1]), "+f"(d[2]), "+f"(d[3])
        : "r"(a[0]), "r"(a[1]), "r"(a[2]), "r"(a[3]), "r"(b0), "r"(b1));
}
__device__ __forceinline__ float ex2(float x){
    float r;
    asm("ex2.approx.ftz.f32 %0, %1;" : "=f"(r) : "f"(x));
    return r;
}
#define L2E 1.44269504f

// ---------------- smem layout -------------------------------------------------
#define PITCH   80
#define MATB    (128*PITCH)      // 10240 bytes per 128x32 fp16 tile (+pad)

// ---------------- tensor-core GEMM (single-sync, 2-stage) ----------------------
// BSPLIT=1: C = A*(Bh+Bl)^T  (2-term)   BSPLIT=0: C = A*Bh^T (1-term)
// A:[M,K] fp16 K-major, B:[N,K] K-major. 256 thr, 8 warps, warp tile 64x32.
// EPI 0: Cf = alpha*D + bias (fp32)
// EPI 2: Ch = fp16(D + bias)
// EPI 3: Ch = fp16(alpha * D)
template<int BSPLIT, int EPI>
__global__ void __launch_bounds__(256, 2)
gemm_mma(const __half* __restrict__ Ah,
         const __half* __restrict__ Bh, const __half* __restrict__ Bl,
         const float* __restrict__ bias,
         float* __restrict__ Cf, __half* __restrict__ Ch,
         int N, int K, float alpha,
         long long sA, long long sB, long long sC)
{
    constexpr int NMAT = 2 + BSPLIT;
    constexpr uint32_t STAGEB = NMAT * MATB;

    extern __shared__ char smem[];
    const uint32_t sb = smem_u32(smem);
    const int tid = threadIdx.x;
    const int wid = tid >> 5, lane = tid & 31;
    const int wr = wid >> 2, wc = wid & 3;
    const int wm0 = wr * 64, wn0 = wc * 32;

    const int row0 = blockIdx.y << 7, col0 = blockIdx.x << 7;
    const long long zA = (long long)blockIdx.z * sA;
    const long long zB = (long long)blockIdx.z * sB;
    const long long zC = (long long)blockIdx.z * sC;

    const __half* gsrc[NMAT];
    gsrc[0] = Ah + zA + (long long)row0 * K;
    gsrc[1] = Bh + zB + (long long)col0 * K;
    if (BSPLIT) gsrc[2] = Bl + zB + (long long)col0 * K;

    const int lrow0 = tid >> 2;
    const int lu    = tid & 3;

    float acc[4][4][4];
#pragma unroll
    for (int i = 0; i < 4; i++)
#pragma unroll
        for (int j = 0; j < 4; j++)
#pragma unroll
            for (int q = 0; q < 4; q++) acc[i][j][q] = 0.0f;

    const int NC = K >> 5;

    auto load_chunk = [&](int stage, int kc) {
        const uint32_t sdst = sb + stage * STAGEB;
#pragma unroll
        for (int m = 0; m < NMAT; m++) {
            const __half* g = gsrc[m] + kc * 32;
#pragma unroll
            for (int it = 0; it < 2; it++) {
                const int row = lrow0 + it * 64;
                cpa16(sdst + m * MATB + row * PITCH + lu * 16,
                      g + (long long)row * K + lu * 8);
            }
        }
    };

    load_chunk(0, 0);
    cpa_commit();

    for (int kc = 0; kc < NC; kc++) {
        const int s = kc & 1;
        cpa_wait<0>();
        __syncthreads();

        const uint32_t sAh = sb + s * STAGEB;
        const uint32_t sBh = sAh + MATB;
        const uint32_t sBl = sAh + 2 * MATB;
        const int lr = lane & 15;
        const int lc = (lane >> 4) * 16;

#pragma unroll
        for (int k16 = 0; k16 < 2; k16++) {
            const uint32_t kb = k16 * 32 + lc;
            uint32_t ah[4][4], bh[2][4], bl[2][4];
#pragma unroll
            for (int i = 0; i < 4; i++)
                ldm_x4(ah[i], sAh + (uint32_t)(wm0 + i * 16 + lr) * PITCH + kb);
#pragma unroll
            for (int jj = 0; jj < 2; jj++) {
                ldm_x4(bh[jj], sBh + (uint32_t)(wn0 + jj * 16 + lr) * PITCH + kb);
                if (BSPLIT) ldm_x4(bl[jj], sBl + (uint32_t)(wn0 + jj * 16 + lr) * PITCH + kb);
            }
            // prefetch next chunk after this stage's reads are issued (single-sync safe)
            if (k16 == 0 && kc + 1 < NC) {
                load_chunk(s ^ 1, kc + 1);
                cpa_commit();
            }
#pragma unroll
            for (int i = 0; i < 4; i++) {
#pragma unroll
                for (int j = 0; j < 4; j++) {
                    const int jj = j >> 1, sel = j & 1;
                    mma16816(acc[i][j], ah[i], bh[jj][sel], bh[jj][sel + 2]);
                    if (BSPLIT)
                        mma16816(acc[i][j], ah[i], bl[jj][sel], bl[jj][sel + 2]);
                }
            }
        }
    }

    // ---------------- epilogue ----------------
    const int er = lane >> 2;
    const int ec = (lane & 3) * 2;
#pragma unroll
    for (int i = 0; i < 4; i++) {
#pragma unroll
        for (int j = 0; j < 4; j++) {
            const int col = col0 + wn0 + j * 8 + ec;
#pragma unroll
            for (int half_m = 0; half_m < 2; half_m++) {
                const int row = row0 + wm0 + i * 16 + er + half_m * 8;
                const float d0 = acc[i][j][half_m * 2 + 0];
                const float d1 = acc[i][j][half_m * 2 + 1];
                if (EPI == 0) {
                    float2 v;
                    v.x = d0 * alpha; v.y = d1 * alpha;
                    if (bias) { v.x += bias[col]; v.y += bias[col + 1]; }
                    *(float2*)(Cf + zC + (long long)row * N + col) = v;
                } else if (EPI == 2) {
                    float f0 = d0 + bias[col];
                    float f1 = d1 + bias[col + 1];
                    *(__half2*)(Ch + zC + (long long)row * N + col) =
                        __halves2half2(__float2half_rn(f0), __float2half_rn(f1));
                } else {
                    *(__half2*)(Ch + zC + (long long)row * N + col) =
                        __halves2half2(__float2half_rn(d0 * alpha), __float2half_rn(d1 * alpha));
                }
            }
        }
    }
}

// ---------------- fused softmax+PV GEMM ----------------------------------------
// out[b, q, e] = (1/sum_q) * sum_t ex2((s[b,q,t]-m_q)*L2E) * Vt[b, e, t]
// A built on the fly from fp16 scores; B = V^T via cp.async. 2-stage, single sync.
#define PV_STAGEB (2*MATB)
__global__ void __launch_bounds__(256, 2)
gemm_pv(const __half* __restrict__ Sc, const float* __restrict__ rowm,
        const float* __restrict__ rowinv, const __half* __restrict__ Vt,
        float* __restrict__ out)
{
    extern __shared__ char smem[];
    const uint32_t sb = smem_u32(smem);
    const int tid = threadIdx.x;
    const int wid = tid >> 5, lane = tid & 31;
    const int wr = wid >> 2, wc = wid & 3;
    const int wm0 = wr * 64, wn0 = wc * 32;

    const int col0 = blockIdx.x << 7, row0 = blockIdx.y << 7, b = blockIdx.z;
    const __half* A  = Sc + ((long long)(b * SS + row0)) * SS;
    const __half* Bv = Vt + ((long long)(b * DD + col0)) * SS;
    float* C = out + ((long long)(b * SS + row0)) * DD;

    // A loader: thread -> (row, 16-half group)
    const int arow  = tid >> 1;
    const int acolh = (tid & 1) * 16;
    const float tm = rowm[b * SS + row0 + arow] * L2E;

    // B loader
    const int brow0 = tid >> 2, bu = tid & 3;

    uint4 areg0, areg1;
    {
        const __half* p = A + (long long)arow * SS + acolh;
        areg0 = *(const uint4*)p;
        areg1 = *(const uint4*)(p + 8);
#pragma unroll
        for (int it = 0; it < 2; it++) {
            const int r = brow0 + it * 64;
            cpa16(sb + MATB + r * PITCH + bu * 16, Bv + (long long)r * SS + bu * 8);
        }
        cpa_commit();
    }

    float acc[4][4][4];
#pragma unroll
    for (int i = 0; i < 4; i++)
#pragma unroll
        for (int j = 0; j < 4; j++)
#pragma unroll
            for (int q = 0; q < 4; q++) acc[i][j][q] = 0.0f;

    const int NC = SS >> 5;   // 64

    for (int kc = 0; kc < NC; kc++) {
        const int s = kc & 1;
        // convert scores -> p = ex2(s*L2E - tm), STS into stage s A tile
        {
            char* d = smem + s * PV_STAGEB + arow * PITCH + acolh * 2;
            __half2 o[8];
            const __half2* h2a = (const __half2*)&areg0;
            const __half2* h2b = (const __half2*)&areg1;
#pragma unroll
            for (int j = 0; j < 4; j++) {
                float2 f = __half22float2(h2a[j]);
                f.x = ex2(fmaf(f.x, L2E, -tm));
                f.y = ex2(fmaf(f.y, L2E, -tm));
                o[j] = __float22half2_rn(f);
            }
#pragma unroll
            for (int j = 0; j < 4; j++) {
                float2 f = __half22float2(h2b[j]);
                f.x = ex2(fmaf(f.x, L2E, -tm));
                f.y = ex2(fmaf(f.y, L2E, -tm));
                o[4 + j] = __float22half2_rn(f);
            }
            *(uint4*)d        = *(uint4*)&o[0];
            *(uint4*)(d + 16) = *(uint4*)&o[4];
        }
        cpa_wait<0>();
        __syncthreads();

        const uint32_t sA = sb + s * PV_STAGEB;
        const uint32_t sB = sA + MATB;
        const int lr = lane & 15;
        const int lc = (lane >> 4) * 16;

#pragma unroll
        for (int k16 = 0; k16 < 2; k16++) {
            const uint32_t kb = k16 * 32 + lc;
            uint32_t ah[4][4], bh[2][4];
#pragma unroll
            for (int i = 0; i < 4; i++)
                ldm_x4(ah[i], sA + (uint32_t)(wm0 + i * 16 + lr) * PITCH + kb);
#pragma unroll
            for (int jj = 0; jj < 2; jj++)
                ldm_x4(bh[jj], sB + (uint32_t)(wn0 + jj * 16 + lr) * PITCH + kb);

            if (k16 == 0 && kc + 1 < NC) {
                const __half* p = A + (long long)arow * SS + (kc + 1) * 32 + acolh;
                areg0 = *(const uint4*)p;
                areg1 = *(const uint4*)(p + 8);
#pragma unroll
                for (int it = 0; it < 2; it++) {
                    const int r = brow0 + it * 64;
                    cpa16(sb + (s ^ 1) * PV_STAGEB + MATB + r * PITCH + bu * 16,
                          Bv + (long long)r * SS + (kc + 1) * 32 + bu * 8);
                }
                cpa_commit();
            }
#pragma unroll
            for (int i = 0; i < 4; i++)
#pragma unroll
                for (int j = 0; j < 4; j++) {
                    const int jj = j >> 1, sel = j & 1;
                    mma16816(acc[i][j], ah[i], bh[jj][sel], bh[jj][sel + 2]);
                }
        }
    }

    // ---------------- epilogue: x (1/sum), fp32 out -----------------------------
    const int er = lane >> 2;
    const int ec = (lane & 3) * 2;
#pragma unroll
    for (int i = 0; i < 4; i++) {
#pragma unroll
        for (int half_m = 0; half_m < 2; half_m++) {
            const int lrow = wm0 + i * 16 + er + half_m * 8;
            const float inv = rowinv[b * SS + row0 + lrow];
#pragma unroll
            for (int j = 0; j < 4; j++) {
                const int col = col0 + wn0 + j * 8 + ec;
                float2 v;
                v.x = acc[i][j][half_m * 2 + 0] * inv;
                v.y = acc[i][j][half_m * 2 + 1] * inv;
                *(float2*)(C + (long long)lrow * DD + col) = v;
            }
        }
    }
}

// ---------------- row stats: max + 1/sum(exp) over 2048 fp16 scores -----------
__global__ void __launch_bounds__(256)
rowstats(const __half* __restrict__ S, float* __restrict__ rowm, float* __restrict__ rowinv)
{
    const long long rb = (long long)blockIdx.x * SS;
    const int t = threadIdx.x;

    const uint4 v4 = *(const uint4*)(S + rb + t * 8);
    const __half2* h2 = (const __half2*)&v4;
    float v[8];
#pragma unroll
    for (int j = 0; j < 4; j++) {
        float2 f = __half22float2(h2[j]);
        v[2*j] = f.x; v[2*j+1] = f.y;
    }
    float m = v[0];
#pragma unroll
    for (int i = 1; i < 8; i++) m = fmaxf(m, v[i]);

    __shared__ float red[8];
#pragma unroll
    for (int o = 16; o > 0; o >>= 1) m = fmaxf(m, __shfl_xor_sync(0xffffffffu, m, o));
    if ((t & 31) == 0) red[t >> 5] = m;
    __syncthreads();
    if (t < 32) {
        float mm = (t < 8) ? red[t] : -INFINITY;
#pragma unroll
        for (int o = 4; o > 0; o >>= 1) mm = fmaxf(mm, __shfl_xor_sync(0xffffffffu, mm, o));
        if (t == 0) red[0] = mm;
    }
    __syncthreads();
    m = red[0];
    __syncthreads();

    const float tm = m * L2E;
    float sum = 0.0f;
#pragma unroll
    for (int i = 0; i < 8; i++) sum += ex2(fmaf(v[i], L2E, -tm));
#pragma unroll
    for (int o = 16; o > 0; o >>= 1) sum += __shfl_xor_sync(0xffffffffu, sum, o);
    if ((t & 31) == 0) red[t >> 5] = sum;
    __syncthreads();
    if (t < 32) {
        float ss = (t < 8) ? red[t] : 0.0f;
#pragma unroll
        for (int o = 4; o > 0; o >>= 1) ss += __shfl_xor_sync(0xffffffffu, ss, o);
        if (t == 0) {
            rowm[blockIdx.x]   = m;
            rowinv[blockIdx.x] = 1.0f / ss;
        }
    }
}

// ---------------- elementwise fp32 -> fp16 ------------------------------------
__global__ void __launch_bounds__(256)
cvt_f32_f16(const float* __restrict__ s, __half* __restrict__ h, int n4)
{
    int i = blockIdx.x * 256 + threadIdx.x;
    if (i >= n4) return;
    float4 v = ((const float4*)s)[i];
    *(__half2*)(h + 4*i)     = __halves2half2(__float2half_rn(v.x), __float2half_rn(v.y));
    *(__half2*)(h + 4*i + 2) = __halves2half2(__float2half_rn(v.z), __float2half_rn(v.w));
}

// ---------------- transpose (+optional split): fp32 [R,C] -> fp16 [C,R] -------
__global__ void __launch_bounds__(256)
transpose_cvt(const float* __restrict__ src, __half* __restrict__ dh, __half* __restrict__ dl,
              int R, int C, long long sS, long long sD)
{
    __shared__ float t[32][33];
    const float* S = src + (long long)blockIdx.z * sS;
    __half* DH = dh + (long long)blockIdx.z * sD;
    const int c0 = blockIdx.x * 32, r0 = blockIdx.y * 32;
    const int tx = threadIdx.x, ty = threadIdx.y;   // (32, 8)
#pragma unroll
    for (int k = 0; k < 4; k++)
        t[ty + 8*k][tx] = S[(long long)(r0 + ty + 8*k) * C + c0 + tx];
    __syncthreads();
    if (dl) {
        __half* DL = dl + (long long)blockIdx.z * sD;
#pragma unroll
        for (int k = 0; k < 4; k++) {
            float f = t[tx][ty + 8*k];
            __half h = __float2half_rn(f);
            __half l = __float2half_rn(f - __half2float(h));
            long long o = (long long)(c0 + ty + 8*k) * R + r0 + tx;
            DH[o] = h; DL[o] = l;
        }
    } else {
#pragma unroll
        for (int k = 0; k < 4; k++) {
            long long o = (long long)(c0 + ty + 8*k) * R + r0 + tx;
            DH[o] = __float2half_rn(t[tx][ty + 8*k]);
        }
    }
}

// -----------------------------------------------------------------------------
extern "C" void kernel_launch(void* const* d_in, const int* in_sizes, int n_in,
                              void* d_out, int out_size)
{
    (void)in_sizes; (void)n_in; (void)out_size;
    const float* x  = (const float*)d_in[0];
    const float* Wq = (const float*)d_in[1];
    const float* bq = (const float*)d_in[2];
    const float* Wk = (const float*)d_in[3];
    const float* bk = (const float*)d_in[4];
    const float* Wv = (const float*)d_in[5];
    const float* bv = (const float*)d_in[6];
    float* out = (float*)d_out;

    __half *xh, *Wth, *Wtl, *Qh, *Kh, *Vth, *Sc;
    float *Vf, *rowm, *rowinv;
    cudaGetSymbolAddress((void**)&xh,   g_xh);
    cudaGetSymbolAddress((void**)&Wth,  g_Wth);  cudaGetSymbolAddress((void**)&Wtl, g_Wtl);
    cudaGetSymbolAddress((void**)&Qh,   g_Qh);
    cudaGetSymbolAddress((void**)&Kh,   g_Kh);
    cudaGetSymbolAddress((void**)&Vf,   g_Vf);
    cudaGetSymbolAddress((void**)&Vth,  g_Vth);
    cudaGetSymbolAddress((void**)&Sc,   g_Sc);
    cudaGetSymbolAddress((void**)&rowm, g_rowm); cudaGetSymbolAddress((void**)&rowinv, g_rowinv);

    const int SMEM_P  = 2 * 3 * MATB;   // 61440 (projections, B split)
    const int SMEM_1  = 2 * 2 * MATB;   // 40960 (1-term scores)
    const int SMEM_PV = 2 * PV_STAGEB;  // 40960
    cudaFuncSetAttribute((const void*)gemm_mma<1,0>, cudaFuncAttributeMaxDynamicSharedMemorySize, SMEM_P);
    cudaFuncSetAttribute((const void*)gemm_mma<1,2>, cudaFuncAttributeMaxDynamicSharedMemorySize, SMEM_P);
    cudaFuncSetAttribute((const void*)gemm_mma<0,3>, cudaFuncAttributeMaxDynamicSharedMemorySize, SMEM_1);
    cudaFuncSetAttribute((const void*)gemm_pv,       cudaFuncAttributeMaxDynamicSharedMemorySize, SMEM_PV);

    const float scale = 1.0f / sqrtf((float)DD);

    // 1-3) transpose+split weights (launches 1-3; ncu -s 5 lands on a GEMM below)
    {
        dim3 tb(32, 8), tg(DD/32, DD/32, 1);
        transpose_cvt<<<tg, tb>>>(Wq, Wth + 0*DD*DD, Wtl + 0*DD*DD, DD, DD, 0, 0);
        transpose_cvt<<<tg, tb>>>(Wk, Wth + 1*DD*DD, Wtl + 1*DD*DD, DD, DD, 0, 0);
        transpose_cvt<<<tg, tb>>>(Wv, Wth + 2*DD*DD, Wtl + 2*DD*DD, DD, DD, 0, 0);
    }
    // 4) x -> fp16
    {
        int n4 = MTOT * DD / 4;
        cvt_f32_f16<<<(n4 + 255) / 256, 256>>>(x, xh, n4);
    }
    // 5-7) projections (M=16384, N=512, K=512), 2-term (W split)
    {
        dim3 g(DD/128, MTOT/128, 1);
        gemm_mma<1,2><<<g, 256, SMEM_P>>>(xh, Wth + 0*DD*DD, Wtl + 0*DD*DD, bq,
                                          nullptr, Qh, DD, DD, 1.0f, 0, 0, 0);
        gemm_mma<1,2><<<g, 256, SMEM_P>>>(xh, Wth + 1*DD*DD, Wtl + 1*DD*DD, bk,
                                          nullptr, Kh, DD, DD, 1.0f, 0, 0, 0);
        gemm_mma<1,0><<<g, 256, SMEM_P>>>(xh, Wth + 2*DD*DD, Wtl + 2*DD*DD, bv,
                                          Vf, nullptr, DD, DD, 1.0f, 0, 0, 0);
    }
    // 8) transpose V per batch: Vf [s,e] -> Vt [e,s] fp16
    {
        dim3 tb(32, 8), tg(DD/32, SS/32, BB);
        transpose_cvt<<<tg, tb>>>(Vf, Vth, nullptr, SS, DD,
                                  (long long)SS*DD, (long long)DD*SS);
    }
    // 9) scores = fp16(scale * Q @ K^T) per batch (M=N=2048, K=512)
    {
        dim3 g(SS/128, SS/128, BB);
        gemm_mma<0,3><<<g, 256, SMEM_1>>>(Qh, Kh, nullptr, nullptr,
                                          nullptr, Sc, SS, DD, scale,
                                          (long long)SS*DD, (long long)SS*DD,
                                          (long long)SS*SS);
    }
    // 10) per-row softmax stats
    rowstats<<<MTOT, 256>>>(Sc, rowm, rowinv);
    // 11) fused softmax+PV: out = softmax(S) @ V per batch
    {
        dim3 g(DD/128, SS/128, BB);
        gemm_pv<<<g, 256, SMEM_PV>>>(Sc, rowm, rowinv, Vth, out);
    }
}